// round 11
// baseline (speedup 1.0000x reference)
#include <cuda_runtime.h>
#include <cuda_bf16.h>
#include <cstdint>

// Problem shapes (fixed by the reference)
#define B_DIM 1024
#define F_DIM 256
#define D_DIM 64
#define N_TOT (F_DIM * D_DIM)   // 16384

// ---------------- device-global scratch (alloc-free) ----------------
__device__ float g_trans[2][F_DIM][D_DIM];            // 128 KB
__device__ float g_qkv[3][F_DIM][D_DIM];              // 192 KB
__device__ float g_qkv2T[D_DIM][F_DIM];               // 64 KB (qkv[2] transposed)
__device__ float g_c[B_DIM][F_DIM];                   // 1 MB   (s0*s2)
__device__ __nv_bfloat16 g_Ahi[B_DIM * F_DIM];        // 512 KB  s1 hi
__device__ __nv_bfloat16 g_Alo[B_DIM * F_DIM];        // 512 KB  s1 lo
__device__ __nv_bfloat16 g_Phi[(size_t)N_TOT * F_DIM];// 8 MB    P hi
__device__ __nv_bfloat16 g_Plo[(size_t)N_TOT * F_DIM];// 8 MB    P lo

// ---------------- PTX helpers (plain sm_103-safe: no tcgen05) -------------
__device__ __forceinline__ uint32_t smem_to_u32(const void* p) {
    uint32_t a;
    asm("{ .reg .u64 t; cvta.to.shared.u64 t, %1; cvt.u32.u64 %0, t; }"
        : "=r"(a) : "l"(p));
    return a;
}

#define CP_ASYNC16(dst, src) \
    asm volatile("cp.async.cg.shared.global [%0], [%1], 16;" \
                 :: "r"(dst), "l"(src))
#define CP_COMMIT() asm volatile("cp.async.commit_group;" ::: "memory")
#define CP_WAIT(n)  asm volatile("cp.async.wait_group %0;" :: "n"(n) : "memory")

#define LDSM4(r, addr) \
    asm volatile("ldmatrix.sync.aligned.m8n8.x4.shared.b16 {%0,%1,%2,%3}, [%4];" \
                 : "=r"((r)[0]), "=r"((r)[1]), "=r"((r)[2]), "=r"((r)[3]) \
                 : "r"(addr))

#define MMA16816(d, a, br0, br1) \
    asm volatile("mma.sync.aligned.m16n8k16.row.col.f32.bf16.bf16.f32 " \
                 "{%0,%1,%2,%3}, {%4,%5,%6,%7}, {%8,%9}, {%0,%1,%2,%3};" \
                 : "+f"((d)[0]), "+f"((d)[1]), "+f"((d)[2]), "+f"((d)[3]) \
                 : "r"((a)[0]), "r"((a)[1]), "r"((a)[2]), "r"((a)[3]), \
                   "r"(br0), "r"(br1))

// ---------------- kernel 1: trans / qkv  (5 tiny 64x64 matmuls)
__global__ void k_transform(const float* __restrict__ ind,
                            const float* __restrict__ Wqk,
                            const float* __restrict__ Wqkv) {
    const int f = blockIdx.x;
    const int n = blockIdx.y;
    const int e = threadIdx.x;
    __shared__ float srow[D_DIM];
    srow[e] = ind[f * D_DIM + e];
    __syncthreads();
    const float* W = (n < 2) ? (Wqk + n * D_DIM * D_DIM)
                             : (Wqkv + (n - 2) * D_DIM * D_DIM);
    float acc = 0.f;
#pragma unroll
    for (int d = 0; d < D_DIM; ++d) acc = fmaf(srow[d], W[d * D_DIM + e], acc);
    if (n < 2) g_trans[n][f][e] = acc;
    else {
        g_qkv[n - 2][f][e] = acc;
        if (n == 4) g_qkv2T[e][f] = acc;   // transposed copy for k_gateP
    }
}

// ---------------- kernel 2 (fused gate + P):
// M[i,j] = (trans0[i].trans1[j] > 0) * (qkv1[i].qkv0[j])
// P[(i,d), j] = M[i,j] * qkv2[j,d], split bf16 hi/lo.
// grid (256 i, 8 d-groups), block 256 (j). Gate dot recomputed per d-group (cheap).
__global__ void k_gateP() {
    const int i  = blockIdx.x;
    const int d0 = blockIdx.y << 3;
    const int j  = threadIdx.x;
    __shared__ float t0[D_DIM];
    __shared__ float q1[D_DIM];
    if (j < D_DIM)            t0[j] = g_trans[0][i][j];
    else if (j < 2 * D_DIM)   q1[j - D_DIM] = g_qkv[1][i][j - D_DIM];
    __syncthreads();
    float d1 = 0.f, d2 = 0.f;
#pragma unroll
    for (int d = 0; d < D_DIM; ++d) {
        d1 = fmaf(t0[d], g_trans[1][j][d], d1);
        d2 = fmaf(q1[d], g_qkv[0][j][d], d2);
    }
    const float m = (d1 > 0.f) ? d2 : 0.f;
    const size_t base = ((size_t)(i << 6) + d0) * F_DIM + j;
#pragma unroll
    for (int dd = 0; dd < 8; ++dd) {
        const float v = m * g_qkv2T[d0 + dd][j];            // coalesced read
        const __nv_bfloat16 hi = __float2bfloat16_rn(v);
        const float lo = v - __bfloat162float(hi);
        g_Phi[base + (size_t)dd * F_DIM] = hi;              // coalesced write
        g_Plo[base + (size_t)dd * F_DIM] = __float2bfloat16_rn(lo);
    }
}

// ---------------- kernel 3: s1 (split bf16 hi/lo) and c = s0*s2
// Warp handles 4 rows: lane = r*8 + c; 8 lanes per row, 8 floats/lane (2x float4).
// Reduction: 3 shfl_xor steps within groups of 8 (9 shfls per 4 rows).
__global__ void k_s(const float* __restrict__ feature) {
    const int warp = (blockIdx.x << 3) + (threadIdx.x >> 5);  // global warp id
    const int lane = threadIdx.x & 31;
    const int r = lane >> 3;          // 0..3  (row within warp)
    const int c = lane & 7;           // 0..7  (chunk within row)
    const int row = (warp << 2) + r;  // 0 .. B*F-1
    const int b = row >> 8;
    const int f = row & 255;

    const float4* fp = reinterpret_cast<const float4*>(
        feature + ((size_t)row << 6) + (c << 3));
    const float4 fv0 = fp[0], fv1 = fp[1];
    const float4* q0p = reinterpret_cast<const float4*>(&g_qkv[0][f][c << 3]);
    const float4* q1p = reinterpret_cast<const float4*>(&g_qkv[1][f][c << 3]);
    const float4* q2p = reinterpret_cast<const float4*>(&g_qkv[2][f][c << 3]);
    const float4 a0 = q0p[0], a1 = q0p[1];
    const float4 b0v = q1p[0], b1v = q1p[1];
    const float4 c0 = q2p[0], c1 = q2p[1];

    float r0 = fv0.x*a0.x + fv0.y*a0.y + fv0.z*a0.z + fv0.w*a0.w
             + fv1.x*a1.x + fv1.y*a1.y + fv1.z*a1.z + fv1.w*a1.w;
    float r1 = fv0.x*b0v.x + fv0.y*b0v.y + fv0.z*b0v.z + fv0.w*b0v.w
             + fv1.x*b1v.x + fv1.y*b1v.y + fv1.z*b1v.z + fv1.w*b1v.w;
    float r2 = fv0.x*c0.x + fv0.y*c0.y + fv0.z*c0.z + fv0.w*c0.w
             + fv1.x*c1.x + fv1.y*c1.y + fv1.z*c1.z + fv1.w*c1.w;
#pragma unroll
    for (int off = 4; off; off >>= 1) {
        r0 += __shfl_xor_sync(0xffffffffu, r0, off);
        r1 += __shfl_xor_sync(0xffffffffu, r1, off);
        r2 += __shfl_xor_sync(0xffffffffu, r2, off);
    }
    if (c == 0) {
        g_c[b][f] = r0 * r2;
        __nv_bfloat16 hi = __float2bfloat16_rn(r1);
        g_Ahi[row] = hi;
        g_Alo[row] = __float2bfloat16_rn(r1 - __bfloat162float(hi));
    }
}

// ---------------- kernel 4: HMMA GEMM  out[b,n] = c[b,n>>6] * (s1 @ P^T)
// CTA tile M=128(b) x N=128(n), K=256 in 8 chunks of 32, cp.async double buffer.
// 8 warps in 4(M) x 2(N); warp tile 32 x 64; mma.m16n8k16 bf16->f32.
// Compensated: acc += Ahi*Bhi + Ahi*Blo + Alo*Bhi (issued term-major for ILP).
static constexpr int SROW_B   = 80;                // bytes per smem row (32 bf16 + 16B pad)
static constexpr int ARR_B    = 128 * SROW_B;      // 10240 per array
static constexpr int STAGE_B  = 4 * ARR_B;         // 40960 per stage (Ahi,Alo,Bhi,Blo)
static constexpr int SMEM_SZ  = 2 * STAGE_B;       // 81920

__global__ __launch_bounds__(256, 2) void k_mma(float* __restrict__ out) {
    extern __shared__ char smem[];
    const uint32_t sb = smem_to_u32(smem);
    const int tid  = threadIdx.x;
    const int wid  = tid >> 5;
    const int lane = tid & 31;
    const int n0 = blockIdx.x << 7;    // 128 n-tiles
    const int b0 = blockIdx.y << 7;    // 8 b-tiles

    const int warp_m = (wid >> 1) * 32;   // 0,32,64,96
    const int warp_n = (wid & 1) * 64;    // 0,64

    // ldmatrix lane address component: row (lane&15), 16B col block (lane>>4)
    const uint32_t laneRC = (uint32_t)((lane & 15) * SROW_B + (lane >> 4) * 16);

    float acc[2][8][4];
#pragma unroll
    for (int mt = 0; mt < 2; ++mt)
#pragma unroll
        for (int nt = 0; nt < 8; ++nt)
#pragma unroll
            for (int e = 0; e < 4; ++e) acc[mt][nt][e] = 0.f;

    // ---- stage loader: 2048 x 16B cp.async (A hi/lo 128x32, B hi/lo 128x32)
    auto load_stage = [&](int st, int ch) {
        const int j0 = ch << 5;
        const uint32_t dst0 = sb + st * STAGE_B;
#pragma unroll
        for (int it = 0; it < 8; ++it) {
            const int e = tid + it * 256;      // 0..2047
            const int arr = e >> 9;            // 0..3
            const int r   = (e >> 2) & 127;
            const int c   = e & 3;
            const uint32_t dst = dst0 + arr * ARR_B + r * SROW_B + c * 16;
            const __nv_bfloat16* src;
            if (arr == 0)      src = g_Ahi + (size_t)(b0 + r) * F_DIM + j0 + c * 8;
            else if (arr == 1) src = g_Alo + (size_t)(b0 + r) * F_DIM + j0 + c * 8;
            else if (arr == 2) src = g_Phi + (size_t)(n0 + r) * F_DIM + j0 + c * 8;
            else               src = g_Plo + (size_t)(n0 + r) * F_DIM + j0 + c * 8;
            CP_ASYNC16(dst, src);
        }
    };

    load_stage(0, 0);
    CP_COMMIT();

    for (int ch = 0; ch < 8; ++ch) {
        const int st = ch & 1;
        if (ch + 1 < 8) {
            load_stage(st ^ 1, ch + 1);
            CP_COMMIT();
            CP_WAIT(1);
        } else {
            CP_WAIT(0);
        }
        __syncthreads();

        const uint32_t aHi = sb + st * STAGE_B + (uint32_t)warp_m * SROW_B + laneRC;
        const uint32_t aLo = aHi + ARR_B;
        const uint32_t bHi = sb + st * STAGE_B + 2 * ARR_B + (uint32_t)warp_n * SROW_B + laneRC;
        const uint32_t bLo = bHi + ARR_B;

#pragma unroll
        for (int ks = 0; ks < 2; ++ks) {
            uint32_t ah[2][4], al[2][4];
#pragma unroll
            for (int mt = 0; mt < 2; ++mt) {
                LDSM4(ah[mt], aHi + mt * 16 * SROW_B + ks * 32);
                LDSM4(al[mt], aLo + mt * 16 * SROW_B + ks * 32);
            }
            // process B in two p-groups of 2 to cap live registers (<=128/thread)
#pragma unroll
            for (int pg = 0; pg < 2; ++pg) {
                uint32_t bh[2][4], bl[2][4];
#pragma unroll
                for (int pi = 0; pi < 2; ++pi) {
                    const int p = pg * 2 + pi;
                    LDSM4(bh[pi], bHi + p * 16 * SROW_B + ks * 32);
                    LDSM4(bl[pi], bLo + p * 16 * SROW_B + ks * 32);
                }
                // term-major issue: 8 independent accumulators per term ->
                // RAW reuse distance 8 instead of 1
#pragma unroll
                for (int mt = 0; mt < 2; ++mt)
#pragma unroll
                    for (int pi = 0; pi < 2; ++pi)
#pragma unroll
                        for (int s = 0; s < 2; ++s)
                            MMA16816(acc[mt][(pg * 2 + pi) * 2 + s],
                                     ah[mt], bh[pi][s], bh[pi][s + 2]);
#pragma unroll
                for (int mt = 0; mt < 2; ++mt)
#pragma unroll
                    for (int pi = 0; pi < 2; ++pi)
#pragma unroll
                        for (int s = 0; s < 2; ++s)
                            MMA16816(acc[mt][(pg * 2 + pi) * 2 + s],
                                     ah[mt], bl[pi][s], bl[pi][s + 2]);
#pragma unroll
                for (int mt = 0; mt < 2; ++mt)
#pragma unroll
                    for (int pi = 0; pi < 2; ++pi)
#pragma unroll
                        for (int s = 0; s < 2; ++s)
                            MMA16816(acc[mt][(pg * 2 + pi) * 2 + s],
                                     al[mt], bh[pi][s], bh[pi][s + 2]);
            }
        }
        __syncthreads();
    }

    // ---- epilogue: scale by c[b,i] (i constant over the warp's 64 n-cols)
    const int i_idx = (n0 + warp_n) >> 6;
#pragma unroll
    for (int mt = 0; mt < 2; ++mt) {
        const int r0 = b0 + warp_m + mt * 16 + (lane >> 2);
        const int r1 = r0 + 8;
        const float cc0 = g_c[r0][i_idx];
        const float cc1 = g_c[r1][i_idx];
#pragma unroll
        for (int nt = 0; nt < 8; ++nt) {
            const int col = n0 + warp_n + nt * 8 + (lane & 3) * 2;
            float2 v0 = { acc[mt][nt][0] * cc0, acc[mt][nt][1] * cc0 };
            float2 v1 = { acc[mt][nt][2] * cc1, acc[mt][nt][3] * cc1 };
            *reinterpret_cast<float2*>(out + (size_t)r0 * N_TOT + col) = v0;
            *reinterpret_cast<float2*>(out + (size_t)r1 * N_TOT + col) = v1;
        }
    }
}

// ---------------- launch ----------------
extern "C" void kernel_launch(void* const* d_in, const int* in_sizes, int n_in,
                              void* d_out, int out_size) {
    const float* feature   = (const float*)d_in[0];  // [1024,256,64]
    const float* indicator = (const float*)d_in[1];  // [256,64]
    const float* W_qk      = (const float*)d_in[2];  // [2,64,64]
    const float* W_qkv     = (const float*)d_in[3];  // [3,64,64]
    float* out = (float*)d_out;                      // [1024,256,64]

    cudaFuncSetAttribute((const void*)k_mma,
                         cudaFuncAttributeMaxDynamicSharedMemorySize, SMEM_SZ);

    // k_mma stays launch #4 — ncu captures launch #4
    k_transform<<<dim3(F_DIM, 5), D_DIM>>>(indicator, W_qk, W_qkv);
    k_gateP<<<dim3(F_DIM, 8), F_DIM>>>();
    k_s<<<(B_DIM * F_DIM) / 32, 256>>>(feature);
    k_mma<<<dim3(N_TOT / 128, B_DIM / 128), 256, SMEM_SZ>>>(out);
}

// round 13
// speedup vs baseline: 2.6786x; 2.6786x over previous
#include <cuda_runtime.h>
#include <cuda_bf16.h>
#include <cstdint>

// Problem shapes (fixed by the reference)
#define B_DIM 1024
#define F_DIM 256
#define D_DIM 64
#define N_TOT (F_DIM * D_DIM)   // 16384

// ---------------- device-global scratch (alloc-free) ----------------
__device__ float g_trans0[F_DIM][D_DIM];              // 64 KB (row-major, for smem t0)
__device__ float g_qkv[3][F_DIM][D_DIM];              // 192 KB
__device__ float g_t1T[D_DIM][F_DIM];                 // 64 KB  trans1 transposed
__device__ float g_q0T[D_DIM][F_DIM];                 // 64 KB  qkv0  transposed
__device__ float g_qkv2T[D_DIM][F_DIM];               // 64 KB  qkv2  transposed
__device__ float g_c[B_DIM][F_DIM];                   // 1 MB   (s0*s2)
__device__ __nv_bfloat16 g_Ahi[B_DIM * F_DIM];        // 512 KB  s1 hi
__device__ __nv_bfloat16 g_Alo[B_DIM * F_DIM];        // 512 KB  s1 lo
__device__ __nv_bfloat16 g_Phi[(size_t)N_TOT * F_DIM];// 8 MB    P hi
__device__ __nv_bfloat16 g_Plo[(size_t)N_TOT * F_DIM];// 8 MB    P lo

// ---------------- PTX helpers (plain sm_103-safe: no tcgen05) -------------
__device__ __forceinline__ uint32_t smem_to_u32(const void* p) {
    uint32_t a;
    asm("{ .reg .u64 t; cvta.to.shared.u64 t, %1; cvt.u32.u64 %0, t; }"
        : "=r"(a) : "l"(p));
    return a;
}

#define CP_ASYNC16(dst, src) \
    asm volatile("cp.async.cg.shared.global [%0], [%1], 16;" \
                 :: "r"(dst), "l"(src))
#define CP_COMMIT() asm volatile("cp.async.commit_group;" ::: "memory")
#define CP_WAIT(n)  asm volatile("cp.async.wait_group %0;" :: "n"(n) : "memory")

#define LDSM4(r, addr) \
    asm volatile("ldmatrix.sync.aligned.m8n8.x4.shared.b16 {%0,%1,%2,%3}, [%4];" \
                 : "=r"((r)[0]), "=r"((r)[1]), "=r"((r)[2]), "=r"((r)[3]) \
                 : "r"(addr))

#define MMA16816(d, a, br0, br1) \
    asm volatile("mma.sync.aligned.m16n8k16.row.col.f32.bf16.bf16.f32 " \
                 "{%0,%1,%2,%3}, {%4,%5,%6,%7}, {%8,%9}, {%0,%1,%2,%3};" \
                 : "+f"((d)[0]), "+f"((d)[1]), "+f"((d)[2]), "+f"((d)[3]) \
                 : "r"((a)[0]), "r"((a)[1]), "r"((a)[2]), "r"((a)[3]), \
                   "r"(br0), "r"(br1))

// ---------------- kernel 1: trans / qkv  (5 tiny 64x64 matmuls)
// n=0: trans0 (row-major). n=1: trans1 -> transposed. n=2: qkv0 (+transposed).
// n=3: qkv1. n=4: qkv2 (+transposed).
__global__ void k_transform(const float* __restrict__ ind,
                            const float* __restrict__ Wqk,
                            const float* __restrict__ Wqkv) {
    const int f = blockIdx.x;
    const int n = blockIdx.y;
    const int e = threadIdx.x;
    __shared__ float srow[D_DIM];
    srow[e] = ind[f * D_DIM + e];
    __syncthreads();
    const float* W = (n < 2) ? (Wqk + n * D_DIM * D_DIM)
                             : (Wqkv + (n - 2) * D_DIM * D_DIM);
    float acc = 0.f;
#pragma unroll
    for (int d = 0; d < D_DIM; ++d) acc = fmaf(srow[d], W[d * D_DIM + e], acc);
    if (n == 0)      g_trans0[f][e] = acc;
    else if (n == 1) g_t1T[e][f] = acc;
    else {
        g_qkv[n - 2][f][e] = acc;
        if (n == 2) g_q0T[e][f] = acc;
        if (n == 4) g_qkv2T[e][f] = acc;
    }
}

// ---------------- kernel 2 (fused gate + P):
// M[i,j] = (trans0[i].trans1[j] > 0) * (qkv1[i].qkv0[j])
// P[(i,d), j] = M[i,j] * qkv2[j,d], split bf16 hi/lo.
// grid (256 i, 2 d-groups of 32), block 256 (j).
// Dot loads are COALESCED via transposed operand arrays (round-11 fix).
__global__ void k_gateP() {
    const int i  = blockIdx.x;
    const int d0 = blockIdx.y << 5;
    const int j  = threadIdx.x;
    __shared__ float t0[D_DIM];
    __shared__ float q1[D_DIM];
    if (j < D_DIM)            t0[j] = g_trans0[i][j];
    else if (j < 2 * D_DIM)   q1[j - D_DIM] = g_qkv[1][i][j - D_DIM];
    __syncthreads();
    float d1 = 0.f, d2 = 0.f;
#pragma unroll 8
    for (int d = 0; d < D_DIM; ++d) {
        d1 = fmaf(t0[d], g_t1T[d][j], d1);    // coalesced across j
        d2 = fmaf(q1[d], g_q0T[d][j], d2);    // coalesced across j
    }
    const float m = (d1 > 0.f) ? d2 : 0.f;
    const size_t base = ((size_t)(i << 6) + d0) * F_DIM + j;
#pragma unroll 8
    for (int dd = 0; dd < 32; ++dd) {
        const float v = m * g_qkv2T[d0 + dd][j];            // coalesced read
        const __nv_bfloat16 hi = __float2bfloat16_rn(v);
        const float lo = v - __bfloat162float(hi);
        g_Phi[base + (size_t)dd * F_DIM] = hi;              // coalesced write
        g_Plo[base + (size_t)dd * F_DIM] = __float2bfloat16_rn(lo);
    }
}

// ---------------- kernel 3: s1 (split bf16 hi/lo) and c = s0*s2
// Warp handles 4 rows: lane = r*8 + c; 8 lanes per row, 8 floats/lane (2x float4).
__global__ void k_s(const float* __restrict__ feature) {
    const int warp = (blockIdx.x << 3) + (threadIdx.x >> 5);  // global warp id
    const int lane = threadIdx.x & 31;
    const int r = lane >> 3;          // 0..3  (row within warp)
    const int c = lane & 7;           // 0..7  (chunk within row)
    const int row = (warp << 2) + r;  // 0 .. B*F-1
    const int b = row >> 8;
    const int f = row & 255;

    const float4* fp = reinterpret_cast<const float4*>(
        feature + ((size_t)row << 6) + (c << 3));
    const float4 fv0 = fp[0], fv1 = fp[1];
    const float4* q0p = reinterpret_cast<const float4*>(&g_qkv[0][f][c << 3]);
    const float4* q1p = reinterpret_cast<const float4*>(&g_qkv[1][f][c << 3]);
    const float4* q2p = reinterpret_cast<const float4*>(&g_qkv[2][f][c << 3]);
    const float4 a0 = q0p[0], a1 = q0p[1];
    const float4 b0v = q1p[0], b1v = q1p[1];
    const float4 c0 = q2p[0], c1 = q2p[1];

    float r0 = fv0.x*a0.x + fv0.y*a0.y + fv0.z*a0.z + fv0.w*a0.w
             + fv1.x*a1.x + fv1.y*a1.y + fv1.z*a1.z + fv1.w*a1.w;
    float r1 = fv0.x*b0v.x + fv0.y*b0v.y + fv0.z*b0v.z + fv0.w*b0v.w
             + fv1.x*b1v.x + fv1.y*b1v.y + fv1.z*b1v.z + fv1.w*b1v.w;
    float r2 = fv0.x*c0.x + fv0.y*c0.y + fv0.z*c0.z + fv0.w*c0.w
             + fv1.x*c1.x + fv1.y*c1.y + fv1.z*c1.z + fv1.w*c1.w;
#pragma unroll
    for (int off = 4; off; off >>= 1) {
        r0 += __shfl_xor_sync(0xffffffffu, r0, off);
        r1 += __shfl_xor_sync(0xffffffffu, r1, off);
        r2 += __shfl_xor_sync(0xffffffffu, r2, off);
    }
    if (c == 0) {
        g_c[b][f] = r0 * r2;
        __nv_bfloat16 hi = __float2bfloat16_rn(r1);
        g_Ahi[row] = hi;
        g_Alo[row] = __float2bfloat16_rn(r1 - __bfloat162float(hi));
    }
}

// ---------------- kernel 4: HMMA GEMM  out[b,n] = c[b,n>>6] * (s1 @ P^T)
// CTA tile M=128(b) x N=128(n), K=256 in 8 chunks of 32, cp.async double buffer.
// 8 warps in 4(M) x 2(N); warp tile 32 x 64; mma.m16n8k16 bf16->f32.
// Compensated: acc += Ahi*Bhi + Ahi*Blo + Alo*Bhi (issued term-major for ILP).
static constexpr int SROW_B   = 80;                // bytes per smem row (32 bf16 + 16B pad)
static constexpr int ARR_B    = 128 * SROW_B;      // 10240 per array
static constexpr int STAGE_B  = 4 * ARR_B;         // 40960 per stage (Ahi,Alo,Bhi,Blo)
static constexpr int SMEM_SZ  = 2 * STAGE_B;       // 81920

__global__ __launch_bounds__(256, 2) void k_mma(float* __restrict__ out) {
    extern __shared__ char smem[];
    const uint32_t sb = smem_to_u32(smem);
    const int tid  = threadIdx.x;
    const int wid  = tid >> 5;
    const int lane = tid & 31;
    const int n0 = blockIdx.x << 7;    // 128 n-tiles
    const int b0 = blockIdx.y << 7;    // 8 b-tiles

    const int warp_m = (wid >> 1) * 32;   // 0,32,64,96
    const int warp_n = (wid & 1) * 64;    // 0,64

    // ldmatrix lane address component: row (lane&15), 16B col block (lane>>4)
    const uint32_t laneRC = (uint32_t)((lane & 15) * SROW_B + (lane >> 4) * 16);

    float acc[2][8][4];
#pragma unroll
    for (int mt = 0; mt < 2; ++mt)
#pragma unroll
        for (int nt = 0; nt < 8; ++nt)
#pragma unroll
            for (int e = 0; e < 4; ++e) acc[mt][nt][e] = 0.f;

    // ---- stage loader: 2048 x 16B cp.async (A hi/lo 128x32, B hi/lo 128x32)
    auto load_stage = [&](int st, int ch) {
        const int j0 = ch << 5;
        const uint32_t dst0 = sb + st * STAGE_B;
#pragma unroll
        for (int it = 0; it < 8; ++it) {
            const int e = tid + it * 256;      // 0..2047
            const int arr = e >> 9;            // 0..3
            const int r   = (e >> 2) & 127;
            const int c   = e & 3;
            const uint32_t dst = dst0 + arr * ARR_B + r * SROW_B + c * 16;
            const __nv_bfloat16* src;
            if (arr == 0)      src = g_Ahi + (size_t)(b0 + r) * F_DIM + j0 + c * 8;
            else if (arr == 1) src = g_Alo + (size_t)(b0 + r) * F_DIM + j0 + c * 8;
            else if (arr == 2) src = g_Phi + (size_t)(n0 + r) * F_DIM + j0 + c * 8;
            else               src = g_Plo + (size_t)(n0 + r) * F_DIM + j0 + c * 8;
            CP_ASYNC16(dst, src);
        }
    };

    load_stage(0, 0);
    CP_COMMIT();

    for (int ch = 0; ch < 8; ++ch) {
        const int st = ch & 1;
        if (ch + 1 < 8) {
            load_stage(st ^ 1, ch + 1);
            CP_COMMIT();
            CP_WAIT(1);
        } else {
            CP_WAIT(0);
        }
        __syncthreads();

        const uint32_t aHi = sb + st * STAGE_B + (uint32_t)warp_m * SROW_B + laneRC;
        const uint32_t aLo = aHi + ARR_B;
        const uint32_t bHi = sb + st * STAGE_B + 2 * ARR_B + (uint32_t)warp_n * SROW_B + laneRC;
        const uint32_t bLo = bHi + ARR_B;

#pragma unroll
        for (int ks = 0; ks < 2; ++ks) {
            uint32_t ah[2][4], al[2][4];
#pragma unroll
            for (int mt = 0; mt < 2; ++mt) {
                LDSM4(ah[mt], aHi + mt * 16 * SROW_B + ks * 32);
                LDSM4(al[mt], aLo + mt * 16 * SROW_B + ks * 32);
            }
            // process B in two p-groups of 2 to cap live registers (<=128/thread)
#pragma unroll
            for (int pg = 0; pg < 2; ++pg) {
                uint32_t bh[2][4], bl[2][4];
#pragma unroll
                for (int pi = 0; pi < 2; ++pi) {
                    const int p = pg * 2 + pi;
                    LDSM4(bh[pi], bHi + p * 16 * SROW_B + ks * 32);
                    LDSM4(bl[pi], bLo + p * 16 * SROW_B + ks * 32);
                }
                // term-major issue: 8 independent accumulators per term ->
                // RAW reuse distance 8 instead of 1
#pragma unroll
                for (int mt = 0; mt < 2; ++mt)
#pragma unroll
                    for (int pi = 0; pi < 2; ++pi)
#pragma unroll
                        for (int s = 0; s < 2; ++s)
                            MMA16816(acc[mt][(pg * 2 + pi) * 2 + s],
                                     ah[mt], bh[pi][s], bh[pi][s + 2]);
#pragma unroll
                for (int mt = 0; mt < 2; ++mt)
#pragma unroll
                    for (int pi = 0; pi < 2; ++pi)
#pragma unroll
                        for (int s = 0; s < 2; ++s)
                            MMA16816(acc[mt][(pg * 2 + pi) * 2 + s],
                                     ah[mt], bl[pi][s], bl[pi][s + 2]);
#pragma unroll
                for (int mt = 0; mt < 2; ++mt)
#pragma unroll
                    for (int pi = 0; pi < 2; ++pi)
#pragma unroll
                        for (int s = 0; s < 2; ++s)
                            MMA16816(acc[mt][(pg * 2 + pi) * 2 + s],
                                     al[mt], bh[pi][s], bh[pi][s + 2]);
            }
        }
        __syncthreads();
    }

    // ---- epilogue: scale by c[b,i] (i constant over the warp's 64 n-cols)
    const int i_idx = (n0 + warp_n) >> 6;
#pragma unroll
    for (int mt = 0; mt < 2; ++mt) {
        const int r0 = b0 + warp_m + mt * 16 + (lane >> 2);
        const int r1 = r0 + 8;
        const float cc0 = g_c[r0][i_idx];
        const float cc1 = g_c[r1][i_idx];
#pragma unroll
        for (int nt = 0; nt < 8; ++nt) {
            const int col = n0 + warp_n + nt * 8 + (lane & 3) * 2;
            float2 v0 = { acc[mt][nt][0] * cc0, acc[mt][nt][1] * cc0 };
            float2 v1 = { acc[mt][nt][2] * cc1, acc[mt][nt][3] * cc1 };
            *reinterpret_cast<float2*>(out + (size_t)r0 * N_TOT + col) = v0;
            *reinterpret_cast<float2*>(out + (size_t)r1 * N_TOT + col) = v1;
        }
    }
}

// ---------------- launch ----------------
extern "C" void kernel_launch(void* const* d_in, const int* in_sizes, int n_in,
                              void* d_out, int out_size) {
    const float* feature   = (const float*)d_in[0];  // [1024,256,64]
    const float* indicator = (const float*)d_in[1];  // [256,64]
    const float* W_qk      = (const float*)d_in[2];  // [2,64,64]
    const float* W_qkv     = (const float*)d_in[3];  // [3,64,64]
    float* out = (float*)d_out;                      // [1024,256,64]

    cudaFuncSetAttribute((const void*)k_mma,
                         cudaFuncAttributeMaxDynamicSharedMemorySize, SMEM_SZ);

    // k_mma stays launch #4 — ncu captures launch #4
    k_transform<<<dim3(F_DIM, 5), D_DIM>>>(indicator, W_qk, W_qkv);
    k_gateP<<<dim3(F_DIM, 2), F_DIM>>>();
    k_s<<<(B_DIM * F_DIM) / 32, 256>>>(feature);
    k_mma<<<dim3(N_TOT / 128, B_DIM / 128), 256, SMEM_SZ>>>(out);
}

// round 14
// speedup vs baseline: 2.7738x; 1.0355x over previous
#include <cuda_runtime.h>
#include <cuda_bf16.h>
#include <cstdint>

// Problem shapes (fixed by the reference)
#define B_DIM 1024
#define F_DIM 256
#define D_DIM 64
#define N_TOT (F_DIM * D_DIM)   // 16384

// ---------------- device-global scratch (alloc-free) ----------------
__device__ float g_trans0[F_DIM][D_DIM];              // 64 KB (row-major, for smem t0)
__device__ float g_qkv[3][F_DIM][D_DIM];              // 192 KB
__device__ float g_t1T[D_DIM][F_DIM];                 // 64 KB  trans1 transposed
__device__ float g_q0T[D_DIM][F_DIM];                 // 64 KB  qkv0  transposed
__device__ float g_qkv2T[D_DIM][F_DIM];               // 64 KB  qkv2  transposed
__device__ float g_c[B_DIM][F_DIM];                   // 1 MB   (s0*s2)
__device__ __nv_bfloat16 g_Ahi[B_DIM * F_DIM];        // 512 KB  s1 hi
__device__ __nv_bfloat16 g_Alo[B_DIM * F_DIM];        // 512 KB  s1 lo
__device__ __nv_bfloat16 g_Phi[(size_t)N_TOT * F_DIM];// 8 MB    P hi
__device__ __nv_bfloat16 g_Plo[(size_t)N_TOT * F_DIM];// 8 MB    P lo

// ---------------- PTX helpers (plain sm_103-safe: no tcgen05) -------------
__device__ __forceinline__ uint32_t smem_to_u32(const void* p) {
    uint32_t a;
    asm("{ .reg .u64 t; cvta.to.shared.u64 t, %1; cvt.u32.u64 %0, t; }"
        : "=r"(a) : "l"(p));
    return a;
}

#define CP_ASYNC16(dst, src) \
    asm volatile("cp.async.cg.shared.global [%0], [%1], 16;" \
                 :: "r"(dst), "l"(src))
#define CP_COMMIT() asm volatile("cp.async.commit_group;" ::: "memory")
#define CP_WAIT(n)  asm volatile("cp.async.wait_group %0;" :: "n"(n) : "memory")

#define LDSM4(r, addr) \
    asm volatile("ldmatrix.sync.aligned.m8n8.x4.shared.b16 {%0,%1,%2,%3}, [%4];" \
                 : "=r"((r)[0]), "=r"((r)[1]), "=r"((r)[2]), "=r"((r)[3]) \
                 : "r"(addr))

#define MMA16816(d, a, br0, br1) \
    asm volatile("mma.sync.aligned.m16n8k16.row.col.f32.bf16.bf16.f32 " \
                 "{%0,%1,%2,%3}, {%4,%5,%6,%7}, {%8,%9}, {%0,%1,%2,%3};" \
                 : "+f"((d)[0]), "+f"((d)[1]), "+f"((d)[2]), "+f"((d)[3]) \
                 : "r"((a)[0]), "r"((a)[1]), "r"((a)[2]), "r"((a)[3]), \
                   "r"(br0), "r"(br1))

// ---------------- transform kernels (5 tiny 64x64 matmuls, split into 2
// launches so k_mma remains launch #4 for ncu capture)
// part a: n=0 trans0 (row-major), n=1 trans1 -> transposed
__global__ void k_transform_a(const float* __restrict__ ind,
                              const float* __restrict__ Wqk) {
    const int f = blockIdx.x;
    const int n = blockIdx.y;
    const int e = threadIdx.x;
    __shared__ float srow[D_DIM];
    srow[e] = ind[f * D_DIM + e];
    __syncthreads();
    const float* W = Wqk + n * D_DIM * D_DIM;
    float acc = 0.f;
#pragma unroll
    for (int d = 0; d < D_DIM; ++d) acc = fmaf(srow[d], W[d * D_DIM + e], acc);
    if (n == 0) g_trans0[f][e] = acc;
    else        g_t1T[e][f] = acc;
}
// part b: n=0 qkv0 (+transposed), n=1 qkv1, n=2 qkv2 (+transposed)
__global__ void k_transform_b(const float* __restrict__ ind,
                              const float* __restrict__ Wqkv) {
    const int f = blockIdx.x;
    const int n = blockIdx.y;
    const int e = threadIdx.x;
    __shared__ float srow[D_DIM];
    srow[e] = ind[f * D_DIM + e];
    __syncthreads();
    const float* W = Wqkv + n * D_DIM * D_DIM;
    float acc = 0.f;
#pragma unroll
    for (int d = 0; d < D_DIM; ++d) acc = fmaf(srow[d], W[d * D_DIM + e], acc);
    g_qkv[n][f][e] = acc;
    if (n == 0) g_q0T[e][f] = acc;
    if (n == 2) g_qkv2T[e][f] = acc;
}

// ---------------- fused prep kernel: gateP (blocks 0..511) + s (blocks 512..8703)
// The two parts are independent (both depend only on the transforms); fusing
// them into one launch lets their waves overlap instead of serializing.
#define GATEP_BLOCKS 512
#define S_BLOCKS     (B_DIM * F_DIM / 32)   // 8192

__global__ __launch_bounds__(256) void k_prep(const float* __restrict__ feature) {
    const int bx = blockIdx.x;

    if (bx < GATEP_BLOCKS) {
        // ---- gate + P:  M[i,j] = (trans0[i].trans1[j] > 0) * (qkv1[i].qkv0[j])
        //      P[(i,d), j] = M[i,j] * qkv2[j,d], split bf16 hi/lo.
        const int i  = bx >> 1;
        const int d0 = (bx & 1) << 5;
        const int j  = threadIdx.x;
        __shared__ float t0[D_DIM];
        __shared__ float q1[D_DIM];
        if (j < D_DIM)            t0[j] = g_trans0[i][j];
        else if (j < 2 * D_DIM)   q1[j - D_DIM] = g_qkv[1][i][j - D_DIM];
        __syncthreads();
        float d1 = 0.f, d2 = 0.f;
#pragma unroll 8
        for (int d = 0; d < D_DIM; ++d) {
            d1 = fmaf(t0[d], g_t1T[d][j], d1);    // coalesced across j
            d2 = fmaf(q1[d], g_q0T[d][j], d2);    // coalesced across j
        }
        const float m = (d1 > 0.f) ? d2 : 0.f;
        const size_t base = ((size_t)(i << 6) + d0) * F_DIM + j;
#pragma unroll 8
        for (int dd = 0; dd < 32; ++dd) {
            const float v = m * g_qkv2T[d0 + dd][j];            // coalesced read
            const __nv_bfloat16 hi = __float2bfloat16_rn(v);
            const float lo = v - __bfloat162float(hi);
            g_Phi[base + (size_t)dd * F_DIM] = hi;              // coalesced write
            g_Plo[base + (size_t)dd * F_DIM] = __float2bfloat16_rn(lo);
        }
    } else {
        // ---- s: s1 (split bf16 hi/lo) and c = s0*s2.
        // Warp handles 4 rows: lane = r*8 + c; 8 lanes/row, 8 floats/lane.
        const int warp = ((bx - GATEP_BLOCKS) << 3) + (threadIdx.x >> 5);
        const int lane = threadIdx.x & 31;
        const int r = lane >> 3;
        const int c = lane & 7;
        const int row = (warp << 2) + r;
        const int b = row >> 8;
        const int f = row & 255;

        const float4* fp = reinterpret_cast<const float4*>(
            feature + ((size_t)row << 6) + (c << 3));
        const float4 fv0 = fp[0], fv1 = fp[1];
        const float4* q0p = reinterpret_cast<const float4*>(&g_qkv[0][f][c << 3]);
        const float4* q1p = reinterpret_cast<const float4*>(&g_qkv[1][f][c << 3]);
        const float4* q2p = reinterpret_cast<const float4*>(&g_qkv[2][f][c << 3]);
        const float4 a0 = q0p[0], a1 = q0p[1];
        const float4 b0v = q1p[0], b1v = q1p[1];
        const float4 c0 = q2p[0], c1 = q2p[1];

        float r0 = fv0.x*a0.x + fv0.y*a0.y + fv0.z*a0.z + fv0.w*a0.w
                 + fv1.x*a1.x + fv1.y*a1.y + fv1.z*a1.z + fv1.w*a1.w;
        float r1 = fv0.x*b0v.x + fv0.y*b0v.y + fv0.z*b0v.z + fv0.w*b0v.w
                 + fv1.x*b1v.x + fv1.y*b1v.y + fv1.z*b1v.z + fv1.w*b1v.w;
        float r2 = fv0.x*c0.x + fv0.y*c0.y + fv0.z*c0.z + fv0.w*c0.w
                 + fv1.x*c1.x + fv1.y*c1.y + fv1.z*c1.z + fv1.w*c1.w;
#pragma unroll
        for (int off = 4; off; off >>= 1) {
            r0 += __shfl_xor_sync(0xffffffffu, r0, off);
            r1 += __shfl_xor_sync(0xffffffffu, r1, off);
            r2 += __shfl_xor_sync(0xffffffffu, r2, off);
        }
        if (c == 0) {
            g_c[b][f] = r0 * r2;
            __nv_bfloat16 hi = __float2bfloat16_rn(r1);
            g_Ahi[row] = hi;
            g_Alo[row] = __float2bfloat16_rn(r1 - __bfloat162float(hi));
        }
    }
}

// ---------------- kernel 4: HMMA GEMM  out[b,n] = c[b,n>>6] * (s1 @ P^T)
// CTA tile M=128(b) x N=128(n), K=256 in 8 chunks of 32, cp.async double buffer.
// 8 warps in 4(M) x 2(N); warp tile 32 x 64; mma.m16n8k16 bf16->f32.
// Compensated: acc += Ahi*Bhi + Ahi*Blo + Alo*Bhi (issued term-major for ILP).
static constexpr int SROW_B   = 80;                // bytes per smem row (32 bf16 + 16B pad)
static constexpr int ARR_B    = 128 * SROW_B;      // 10240 per array
static constexpr int STAGE_B  = 4 * ARR_B;         // 40960 per stage (Ahi,Alo,Bhi,Blo)
static constexpr int SMEM_SZ  = 2 * STAGE_B;       // 81920

__global__ __launch_bounds__(256, 2) void k_mma(float* __restrict__ out) {
    extern __shared__ char smem[];
    const uint32_t sb = smem_to_u32(smem);
    const int tid  = threadIdx.x;
    const int wid  = tid >> 5;
    const int lane = tid & 31;
    const int n0 = blockIdx.x << 7;    // 128 n-tiles
    const int b0 = blockIdx.y << 7;    // 8 b-tiles

    const int warp_m = (wid >> 1) * 32;   // 0,32,64,96
    const int warp_n = (wid & 1) * 64;    // 0,64

    // ldmatrix lane address component: row (lane&15), 16B col block (lane>>4)
    const uint32_t laneRC = (uint32_t)((lane & 15) * SROW_B + (lane >> 4) * 16);

    float acc[2][8][4];
#pragma unroll
    for (int mt = 0; mt < 2; ++mt)
#pragma unroll
        for (int nt = 0; nt < 8; ++nt)
#pragma unroll
            for (int e = 0; e < 4; ++e) acc[mt][nt][e] = 0.f;

    // ---- stage loader: 2048 x 16B cp.async (A hi/lo 128x32, B hi/lo 128x32)
    auto load_stage = [&](int st, int ch) {
        const int j0 = ch << 5;
        const uint32_t dst0 = sb + st * STAGE_B;
#pragma unroll
        for (int it = 0; it < 8; ++it) {
            const int e = tid + it * 256;      // 0..2047
            const int arr = e >> 9;            // 0..3
            const int r   = (e >> 2) & 127;
            const int c   = e & 3;
            const uint32_t dst = dst0 + arr * ARR_B + r * SROW_B + c * 16;
            const __nv_bfloat16* src;
            if (arr == 0)      src = g_Ahi + (size_t)(b0 + r) * F_DIM + j0 + c * 8;
            else if (arr == 1) src = g_Alo + (size_t)(b0 + r) * F_DIM + j0 + c * 8;
            else if (arr == 2) src = g_Phi + (size_t)(n0 + r) * F_DIM + j0 + c * 8;
            else               src = g_Plo + (size_t)(n0 + r) * F_DIM + j0 + c * 8;
            CP_ASYNC16(dst, src);
        }
    };

    load_stage(0, 0);
    CP_COMMIT();

    for (int ch = 0; ch < 8; ++ch) {
        const int st = ch & 1;
        if (ch + 1 < 8) {
            load_stage(st ^ 1, ch + 1);
            CP_COMMIT();
            CP_WAIT(1);
        } else {
            CP_WAIT(0);
        }
        __syncthreads();

        const uint32_t aHi = sb + st * STAGE_B + (uint32_t)warp_m * SROW_B + laneRC;
        const uint32_t aLo = aHi + ARR_B;
        const uint32_t bHi = sb + st * STAGE_B + 2 * ARR_B + (uint32_t)warp_n * SROW_B + laneRC;
        const uint32_t bLo = bHi + ARR_B;

#pragma unroll
        for (int ks = 0; ks < 2; ++ks) {
            uint32_t ah[2][4], al[2][4];
#pragma unroll
            for (int mt = 0; mt < 2; ++mt) {
                LDSM4(ah[mt], aHi + mt * 16 * SROW_B + ks * 32);
                LDSM4(al[mt], aLo + mt * 16 * SROW_B + ks * 32);
            }
            // process B in two p-groups of 2 to cap live registers (<=128/thread)
#pragma unroll
            for (int pg = 0; pg < 2; ++pg) {
                uint32_t bh[2][4], bl[2][4];
#pragma unroll
                for (int pi = 0; pi < 2; ++pi) {
                    const int p = pg * 2 + pi;
                    LDSM4(bh[pi], bHi + p * 16 * SROW_B + ks * 32);
                    LDSM4(bl[pi], bLo + p * 16 * SROW_B + ks * 32);
                }
                // term-major issue: 8 independent accumulators per term ->
                // RAW reuse distance 8 instead of 1
#pragma unroll
                for (int mt = 0; mt < 2; ++mt)
#pragma unroll
                    for (int pi = 0; pi < 2; ++pi)
#pragma unroll
                        for (int s = 0; s < 2; ++s)
                            MMA16816(acc[mt][(pg * 2 + pi) * 2 + s],
                                     ah[mt], bh[pi][s], bh[pi][s + 2]);
#pragma unroll
                for (int mt = 0; mt < 2; ++mt)
#pragma unroll
                    for (int pi = 0; pi < 2; ++pi)
#pragma unroll
                        for (int s = 0; s < 2; ++s)
                            MMA16816(acc[mt][(pg * 2 + pi) * 2 + s],
                                     ah[mt], bl[pi][s], bl[pi][s + 2]);
#pragma unroll
                for (int mt = 0; mt < 2; ++mt)
#pragma unroll
                    for (int pi = 0; pi < 2; ++pi)
#pragma unroll
                        for (int s = 0; s < 2; ++s)
                            MMA16816(acc[mt][(pg * 2 + pi) * 2 + s],
                                     al[mt], bh[pi][s], bh[pi][s + 2]);
            }
        }
        __syncthreads();
    }

    // ---- epilogue: scale by c[b,i] (i constant over the warp's 64 n-cols)
    const int i_idx = (n0 + warp_n) >> 6;
#pragma unroll
    for (int mt = 0; mt < 2; ++mt) {
        const int r0 = b0 + warp_m + mt * 16 + (lane >> 2);
        const int r1 = r0 + 8;
        const float cc0 = g_c[r0][i_idx];
        const float cc1 = g_c[r1][i_idx];
#pragma unroll
        for (int nt = 0; nt < 8; ++nt) {
            const int col = n0 + warp_n + nt * 8 + (lane & 3) * 2;
            float2 v0 = { acc[mt][nt][0] * cc0, acc[mt][nt][1] * cc0 };
            float2 v1 = { acc[mt][nt][2] * cc1, acc[mt][nt][3] * cc1 };
            *reinterpret_cast<float2*>(out + (size_t)r0 * N_TOT + col) = v0;
            *reinterpret_cast<float2*>(out + (size_t)r1 * N_TOT + col) = v1;
        }
    }
}

// ---------------- launch ----------------
extern "C" void kernel_launch(void* const* d_in, const int* in_sizes, int n_in,
                              void* d_out, int out_size) {
    const float* feature   = (const float*)d_in[0];  // [1024,256,64]
    const float* indicator = (const float*)d_in[1];  // [256,64]
    const float* W_qk      = (const float*)d_in[2];  // [2,64,64]
    const float* W_qkv     = (const float*)d_in[3];  // [3,64,64]
    float* out = (float*)d_out;                      // [1024,256,64]

    cudaFuncSetAttribute((const void*)k_mma,
                         cudaFuncAttributeMaxDynamicSharedMemorySize, SMEM_SZ);

    // 4 launches; k_mma is launch #4 (ncu captures launch #4)
    k_transform_a<<<dim3(F_DIM, 2), D_DIM>>>(indicator, W_qk);
    k_transform_b<<<dim3(F_DIM, 3), D_DIM>>>(indicator, W_qkv);
    k_prep<<<GATEP_BLOCKS + S_BLOCKS, 256>>>(feature);
    k_mma<<<dim3(N_TOT / 128, B_DIM / 128), 256, SMEM_SZ>>>(out);
}